// round 1
// baseline (speedup 1.0000x reference)
#include <cuda_runtime.h>

typedef unsigned long long ull;

#define BATCH 16
#define DIM   256
#define NSEQ  8192
#define QKV_ROWS 384
#define HEADS 4
#define DHEAD 32
#define HID   128

// Scratch (device globals — no runtime allocation allowed)
__device__ float g_qkv[(size_t)BATCH * QKV_ROWS * NSEQ];   // q raw | exp(k) | v
__device__ float g_C[BATCH * HEADS * DHEAD * DHEAD];       // context numerator
__device__ float g_S[BATCH * HEADS * DHEAD];               // softmax denominator
__device__ float g_G[BATCH * DIM * HID];                   // collapsed tail matrix

// ---------- packed f32x2 helpers (FFMA2) ----------
__device__ __forceinline__ ull ffma2(ull a, ull b, ull c) {
    ull d;
    asm("fma.rn.f32x2 %0, %1, %2, %3;" : "=l"(d) : "l"(a), "l"(b), "l"(c));
    return d;
}
__device__ __forceinline__ ull pdup(float x) {
    ull r; asm("mov.b64 %0, {%1, %1};" : "=l"(r) : "f"(x)); return r;
}
__device__ __forceinline__ ull pk2(float x, float y) {
    ull r; asm("mov.b64 %0, {%1, %2};" : "=l"(r) : "f"(x), "f"(y)); return r;
}
__device__ __forceinline__ void upk(ull v, float& x, float& y) {
    asm("mov.b64 {%0, %1}, %2;" : "=f"(x), "=f"(y) : "l"(v));
}

// ---------- K0: zero the accumulators (must run every replay) ----------
__global__ void k_zero() {
    int i = blockIdx.x * 256 + threadIdx.x;
    if (i < BATCH * HEADS * DHEAD * DHEAD) g_C[i] = 0.0f;
    if (i < BATCH * HEADS * DHEAD)         g_S[i] = 0.0f;
}

// ---------- K1: qkv = w_qkv @ x ; store q raw, exp(k), v raw ----------
// grid (N/128, 3 row-groups, B), block 256. 128x128 tile, BK=16, f32x2 accum.
__global__ __launch_bounds__(256, 2) void k_qkv(const float* __restrict__ x,
                                                const float* __restrict__ w) {
    const int b    = blockIdx.z;
    const int grp  = blockIdx.y;          // 0=q, 1=k, 2=v
    const int rowBase = grp * 128;
    const int nBase   = blockIdx.x * 128;
    const int tid = threadIdx.x;
    const int ty = tid >> 4, tx = tid & 15;

    __shared__ float As[16][128];   // [kk][m]
    __shared__ float Bs[16][128];   // [kk][n]

    ull acc[8][4];
#pragma unroll
    for (int i = 0; i < 8; i++)
#pragma unroll
        for (int j = 0; j < 4; j++) acc[i][j] = 0ull;

    const int lr  = tid >> 2;           // 0..63
    const int lk  = (tid & 3) << 2;     // 0,4,8,12
    const int lkb = tid >> 5;           // 0..7
    const int ln  = (tid & 31) << 2;    // 0..124

    const float* xb = x + (size_t)b * DIM * NSEQ + nBase;

    for (int k0 = 0; k0 < DIM; k0 += 16) {
#pragma unroll
        for (int ri = 0; ri < 2; ri++) {
            const int r = lr + ri * 64;
            float4 t = *(const float4*)(w + (size_t)(rowBase + r) * DIM + k0 + lk);
            As[lk + 0][r] = t.x; As[lk + 1][r] = t.y;
            As[lk + 2][r] = t.z; As[lk + 3][r] = t.w;
        }
#pragma unroll
        for (int ki = 0; ki < 2; ki++) {
            const int kk = lkb + ki * 8;
            *(float4*)&Bs[kk][ln] = *(const float4*)(xb + (size_t)(k0 + kk) * NSEQ + ln);
        }
        __syncthreads();
#pragma unroll
        for (int kk = 0; kk < 16; kk++) {
            float4 a0 = *(const float4*)&As[kk][ty * 8];
            float4 a1 = *(const float4*)&As[kk][ty * 8 + 4];
            float4 b0 = *(const float4*)&Bs[kk][tx * 4];
            float4 b1 = *(const float4*)&Bs[kk][64 + tx * 4];
            ull bb[4] = { pk2(b0.x, b0.y), pk2(b0.z, b0.w),
                          pk2(b1.x, b1.y), pk2(b1.z, b1.w) };
            ull aa[8] = { pdup(a0.x), pdup(a0.y), pdup(a0.z), pdup(a0.w),
                          pdup(a1.x), pdup(a1.y), pdup(a1.z), pdup(a1.w) };
#pragma unroll
            for (int i = 0; i < 8; i++)
#pragma unroll
                for (int j = 0; j < 4; j++)
                    acc[i][j] = ffma2(aa[i], bb[j], acc[i][j]);
        }
        __syncthreads();
    }

    float* outp = g_qkv + (size_t)b * QKV_ROWS * NSEQ + nBase;
#pragma unroll
    for (int i = 0; i < 8; i++) {
        const int o = rowBase + ty * 8 + i;
        float v0, v1, v2, v3, v4, v5, v6, v7;
        upk(acc[i][0], v0, v1); upk(acc[i][1], v2, v3);
        upk(acc[i][2], v4, v5); upk(acc[i][3], v6, v7);
        if (grp == 1) {   // k rows: store exp(k) (softmax w/o max-shift; |k|<~7 is safe)
            v0 = __expf(v0); v1 = __expf(v1); v2 = __expf(v2); v3 = __expf(v3);
            v4 = __expf(v4); v5 = __expf(v5); v6 = __expf(v6); v7 = __expf(v7);
        }
        float* rowp = outp + (size_t)o * NSEQ;
        *(float4*)(rowp + tx * 4)      = make_float4(v0, v1, v2, v3);
        *(float4*)(rowp + 64 + tx * 4) = make_float4(v4, v5, v6, v7);
    }
}

// ---------- K2: C[b,h,d,e] += sum_n ek[d,n] v[e,n];  S[b,h,d] += sum_n ek[d,n] ----------
// grid (N/128, HEADS, B), block 256
__global__ __launch_bounds__(256) void k_ctx() {
    const int b = blockIdx.z, h = blockIdx.y;
    const int nBase = blockIdx.x * 128;
    const int tid = threadIdx.x;

    __shared__ float ek[32][129];
    __shared__ float vv[32][129];

    const float* ekg = g_qkv + ((size_t)(b * QKV_ROWS + 128 + h * DHEAD)) * NSEQ + nBase;
    const float* vg  = g_qkv + ((size_t)(b * QKV_ROWS + 256 + h * DHEAD)) * NSEQ + nBase;

    for (int i = tid; i < 32 * 32; i += 256) {
        int r = i >> 5, c4 = (i & 31) << 2;
        float4 t = *(const float4*)(ekg + (size_t)r * NSEQ + c4);
        ek[r][c4 + 0] = t.x; ek[r][c4 + 1] = t.y; ek[r][c4 + 2] = t.z; ek[r][c4 + 3] = t.w;
        float4 u = *(const float4*)(vg + (size_t)r * NSEQ + c4);
        vv[r][c4 + 0] = u.x; vv[r][c4 + 1] = u.y; vv[r][c4 + 2] = u.z; vv[r][c4 + 3] = u.w;
    }
    __syncthreads();

    const int d  = tid >> 3;
    const int e0 = (tid & 7) << 2;
    float a0 = 0.f, a1 = 0.f, a2 = 0.f, a3 = 0.f, s = 0.f;
#pragma unroll 8
    for (int n = 0; n < 128; n++) {
        float kv = ek[d][n];
        s  += kv;
        a0 += kv * vv[e0 + 0][n];
        a1 += kv * vv[e0 + 1][n];
        a2 += kv * vv[e0 + 2][n];
        a3 += kv * vv[e0 + 3][n];
    }
    float* Cb = g_C + (size_t)(((b * HEADS + h) * DHEAD + d) * DHEAD + e0);
    atomicAdd(Cb + 0, a0); atomicAdd(Cb + 1, a1);
    atomicAdd(Cb + 2, a2); atomicAdd(Cb + 3, a3);
    if (e0 == 0) atomicAdd(g_S + (b * HEADS + h) * DHEAD + d, s);
}

// ---------- K3: G[b][o][h*32+d] = (sum_e w_out[o][h*32+e] * C[b,h,d,e]) / S[b,h,d] ----------
// grid (B), block 256 (one thread per output row o)
__global__ __launch_bounds__(256) void k_G(const float* __restrict__ w_out) {
    const int b = blockIdx.x;
    const int o = threadIdx.x;

    __shared__ float Cs[HEADS * DHEAD * DHEAD];   // 4096
    __shared__ float Ss[HEADS * DHEAD];           // 128

    for (int i = threadIdx.x; i < HEADS * DHEAD * DHEAD; i += 256)
        Cs[i] = g_C[(size_t)b * HEADS * DHEAD * DHEAD + i];
    if (threadIdx.x < HEADS * DHEAD)
        Ss[threadIdx.x] = g_S[(size_t)b * HEADS * DHEAD + threadIdx.x];
    __syncthreads();

    float* Gp = g_G + ((size_t)b * DIM + o) * HID;
#pragma unroll
    for (int h = 0; h < HEADS; h++) {
        float wr[DHEAD];
#pragma unroll
        for (int e = 0; e < DHEAD; e++) wr[e] = w_out[(size_t)o * HID + h * DHEAD + e];
#pragma unroll 4
        for (int d = 0; d < DHEAD; d++) {
            float acc = 0.f;
#pragma unroll
            for (int e = 0; e < DHEAD; e++)
                acc += wr[e] * Cs[(h * DHEAD + d) * DHEAD + e];
            Gp[h * DHEAD + d] = acc / Ss[h * DHEAD + d];
        }
    }
}

// ---------- K4: out = G_b @ q_b + b_out ----------
// grid (N/128, 2 row-groups, B), block 256. K=128, f32x2 accum.
__global__ __launch_bounds__(256, 2) void k_out(const float* __restrict__ bias,
                                                float* __restrict__ out) {
    const int b    = blockIdx.z;
    const int rowBase = blockIdx.y * 128;
    const int nBase   = blockIdx.x * 128;
    const int tid = threadIdx.x;
    const int ty = tid >> 4, tx = tid & 15;

    __shared__ float As[16][128];
    __shared__ float Bs[16][128];

    ull acc[8][4];
#pragma unroll
    for (int i = 0; i < 8; i++)
#pragma unroll
        for (int j = 0; j < 4; j++) acc[i][j] = 0ull;

    const int lr  = tid >> 2;
    const int lk  = (tid & 3) << 2;
    const int lkb = tid >> 5;
    const int ln  = (tid & 31) << 2;

    const float* A  = g_G + (size_t)b * DIM * HID;
    const float* Bq = g_qkv + (size_t)b * QKV_ROWS * NSEQ + nBase;  // q = rows [0,128)

    for (int k0 = 0; k0 < HID; k0 += 16) {
#pragma unroll
        for (int ri = 0; ri < 2; ri++) {
            const int r = lr + ri * 64;
            float4 t = *(const float4*)(A + (size_t)(rowBase + r) * HID + k0 + lk);
            As[lk + 0][r] = t.x; As[lk + 1][r] = t.y;
            As[lk + 2][r] = t.z; As[lk + 3][r] = t.w;
        }
#pragma unroll
        for (int ki = 0; ki < 2; ki++) {
            const int kk = lkb + ki * 8;
            *(float4*)&Bs[kk][ln] = *(const float4*)(Bq + (size_t)(k0 + kk) * NSEQ + ln);
        }
        __syncthreads();
#pragma unroll
        for (int kk = 0; kk < 16; kk++) {
            float4 a0 = *(const float4*)&As[kk][ty * 8];
            float4 a1 = *(const float4*)&As[kk][ty * 8 + 4];
            float4 b0 = *(const float4*)&Bs[kk][tx * 4];
            float4 b1 = *(const float4*)&Bs[kk][64 + tx * 4];
            ull bb[4] = { pk2(b0.x, b0.y), pk2(b0.z, b0.w),
                          pk2(b1.x, b1.y), pk2(b1.z, b1.w) };
            ull aa[8] = { pdup(a0.x), pdup(a0.y), pdup(a0.z), pdup(a0.w),
                          pdup(a1.x), pdup(a1.y), pdup(a1.z), pdup(a1.w) };
#pragma unroll
            for (int i = 0; i < 8; i++)
#pragma unroll
                for (int j = 0; j < 4; j++)
                    acc[i][j] = ffma2(aa[i], bb[j], acc[i][j]);
        }
        __syncthreads();
    }

    float* outb = out + (size_t)b * DIM * NSEQ + nBase;
#pragma unroll
    for (int i = 0; i < 8; i++) {
        const int o = rowBase + ty * 8 + i;
        const float bi = bias[o];
        float v0, v1, v2, v3, v4, v5, v6, v7;
        upk(acc[i][0], v0, v1); upk(acc[i][1], v2, v3);
        upk(acc[i][2], v4, v5); upk(acc[i][3], v6, v7);
        float* rowp = outb + (size_t)o * NSEQ;
        *(float4*)(rowp + tx * 4)      = make_float4(v0 + bi, v1 + bi, v2 + bi, v3 + bi);
        *(float4*)(rowp + 64 + tx * 4) = make_float4(v4 + bi, v5 + bi, v6 + bi, v7 + bi);
    }
}

extern "C" void kernel_launch(void* const* d_in, const int* in_sizes, int n_in,
                              void* d_out, int out_size) {
    const float* x     = (const float*)d_in[0];
    const float* w_qkv = (const float*)d_in[1];
    const float* w_out = (const float*)d_in[2];
    const float* b_out = (const float*)d_in[3];
    float* out = (float*)d_out;

    k_zero<<<257, 256>>>();
    k_qkv<<<dim3(NSEQ / 128, 3, BATCH), 256>>>(x, w_qkv);
    k_ctx<<<dim3(NSEQ / 128, HEADS, BATCH), 256>>>();
    k_G<<<BATCH, 256>>>(w_out);
    k_out<<<dim3(NSEQ / 128, 2, BATCH), 256>>>(b_out, out);
}

// round 3
// speedup vs baseline: 1.1487x; 1.1487x over previous
#include <cuda_runtime.h>
#include <cstdint>

#define BATCH 16
#define DIM   256
#define NSEQ  8192
#define QKV_ROWS 384
#define HEADS 4
#define DHEAD 32
#define HID   128

// Scratch (device globals — no runtime allocation allowed)
__device__ float g_qkv[(size_t)BATCH * QKV_ROWS * NSEQ];   // q raw | exp(k) | v
__device__ float g_C[BATCH * HEADS * DHEAD * DHEAD];       // context numerator
__device__ float g_S[BATCH * HEADS * DHEAD];               // softmax denominator
__device__ float g_G[BATCH * DIM * HID];                   // collapsed tail matrix

// ===================== mma.sync tf32 helpers (sm_80+ PTX, legal on sm_103) =====================
#define MMA_TF32(d, a0, a1, a2, a3, b0, b1) \
    asm volatile("mma.sync.aligned.m16n8k8.row.col.f32.tf32.tf32.f32 " \
        "{%0,%1,%2,%3}, {%4,%5,%6,%7}, {%8,%9}, {%0,%1,%2,%3};" \
        : "+f"((d)[0]), "+f"((d)[1]), "+f"((d)[2]), "+f"((d)[3]) \
        : "r"(a0), "r"(a1), "r"(a2), "r"(a3), "r"(b0), "r"(b1))

__device__ __forceinline__ float tf32_rna(float x) {
    uint32_t h;
    asm("cvt.rna.tf32.f32 %0, %1;" : "=r"(h) : "f"(x));
    return __uint_as_float(h);
}
__device__ __forceinline__ void tf32_split4(float4 t, float4& hi, float4& lo) {
    hi.x = tf32_rna(t.x); lo.x = tf32_rna(t.x - hi.x);
    hi.y = tf32_rna(t.y); lo.y = tf32_rna(t.y - hi.y);
    hi.z = tf32_rna(t.z); lo.z = tf32_rna(t.z - hi.z);
    hi.w = tf32_rna(t.w); lo.w = tf32_rna(t.w - hi.w);
}

// Shared layout (floats), conflict-free for fragment loads:
//   A_hi [128][36], A_lo [128][36]  (m-major, pad 36)
//   B_hi [32][136], B_lo [32][136]  (k-major, pad 136)
#define A_HI 0
#define A_LO 4608
#define B_HI 9216
#define B_LO 13568
#define SM_FLOATS 17920
#define DSMEM_BYTES (SM_FLOATS * 4)

// ---------- K0: zero the accumulators ----------
__global__ void k_zero() {
    int i = blockIdx.x * 256 + threadIdx.x;
    if (i < BATCH * HEADS * DHEAD * DHEAD) g_C[i] = 0.0f;
    if (i < BATCH * HEADS * DHEAD)         g_S[i] = 0.0f;
}

// ---------- K1: qkv = w_qkv @ x via mma.sync tf32 3-pass ----------
// grid (N/128, 3, B), block 256. CTA tile 128x128, K=256 in 8 chunks of 32.
__global__ __launch_bounds__(256, 2) void k_qkv_mma(const float* __restrict__ x,
                                                    const float* __restrict__ w) {
    extern __shared__ float sm[];
    const int b       = blockIdx.z;
    const int grp     = blockIdx.y;            // 0=q, 1=k, 2=v
    const int rowBase = grp * 128;
    const int nBase   = blockIdx.x * 128;
    const int tid     = threadIdx.x;
    const int lane    = tid & 31;
    const int wid     = tid >> 5;
    const int warp_m  = wid & 1;               // 0..1 -> 64 rows
    const int warp_n  = wid >> 1;              // 0..3 -> 32 cols

    const float* xb = x + (size_t)b * DIM * NSEQ + nBase;

    float acc[4][4][4];
#pragma unroll
    for (int i = 0; i < 4; i++)
#pragma unroll
        for (int j = 0; j < 4; j++)
#pragma unroll
            for (int c = 0; c < 4; c++) acc[i][j][c] = 0.0f;

    const int lg = lane >> 2;   // 0..7
    const int lc = lane & 3;    // 0..3

    for (int chunk = 0; chunk < 8; chunk++) {
        const int k0 = chunk * 32;

        // load A: W[rowBase..+128][k0..+32] -> hi/lo, layout [m][36]
#pragma unroll
        for (int it = 0; it < 4; it++) {
            const int i  = tid + it * 256;
            const int r  = i >> 3;
            const int c4 = (i & 7) << 2;
            float4 t = *(const float4*)(w + (size_t)(rowBase + r) * DIM + k0 + c4);
            float4 hi, lo; tf32_split4(t, hi, lo);
            *(float4*)&sm[A_HI + r * 36 + c4] = hi;
            *(float4*)&sm[A_LO + r * 36 + c4] = lo;
        }
        // load B: X[k0..+32][nBase..+128] -> hi/lo, layout [k][136]
#pragma unroll
        for (int it = 0; it < 4; it++) {
            const int i  = tid + it * 256;
            const int k  = i >> 5;
            const int n4 = (i & 31) << 2;
            float4 t = *(const float4*)(xb + (size_t)(k0 + k) * NSEQ + n4);
            float4 hi, lo; tf32_split4(t, hi, lo);
            *(float4*)&sm[B_HI + k * 136 + n4] = hi;
            *(float4*)&sm[B_LO + k * 136 + n4] = lo;
        }
        __syncthreads();

#pragma unroll
        for (int ks = 0; ks < 4; ks++) {
            const int kb = ks * 8;
            uint32_t bh[4][2], bl[4][2];
#pragma unroll
            for (int nt = 0; nt < 4; nt++) {
                const int n0 = warp_n * 32 + nt * 8 + lg;
                const int r0 = (kb + lc) * 136 + n0;
                bh[nt][0] = __float_as_uint(sm[B_HI + r0]);
                bh[nt][1] = __float_as_uint(sm[B_HI + r0 + 4 * 136]);
                bl[nt][0] = __float_as_uint(sm[B_LO + r0]);
                bl[nt][1] = __float_as_uint(sm[B_LO + r0 + 4 * 136]);
            }
#pragma unroll
            for (int mt = 0; mt < 4; mt++) {
                const int m0 = warp_m * 64 + mt * 16 + lg;
                const int a0o = m0 * 36 + kb + lc;
                const uint32_t ah0 = __float_as_uint(sm[A_HI + a0o]);
                const uint32_t ah1 = __float_as_uint(sm[A_HI + a0o + 8 * 36]);
                const uint32_t ah2 = __float_as_uint(sm[A_HI + a0o + 4]);
                const uint32_t ah3 = __float_as_uint(sm[A_HI + a0o + 8 * 36 + 4]);
                const uint32_t al0 = __float_as_uint(sm[A_LO + a0o]);
                const uint32_t al1 = __float_as_uint(sm[A_LO + a0o + 8 * 36]);
                const uint32_t al2 = __float_as_uint(sm[A_LO + a0o + 4]);
                const uint32_t al3 = __float_as_uint(sm[A_LO + a0o + 8 * 36 + 4]);
#pragma unroll
                for (int nt = 0; nt < 4; nt++) {
                    MMA_TF32(acc[mt][nt], ah0, ah1, ah2, ah3, bh[nt][0], bh[nt][1]);
                    MMA_TF32(acc[mt][nt], ah0, ah1, ah2, ah3, bl[nt][0], bl[nt][1]);
                    MMA_TF32(acc[mt][nt], al0, al1, al2, al3, bh[nt][0], bh[nt][1]);
                }
            }
        }
        __syncthreads();
    }

    // epilogue: exp() for the k group, store float2 pairs
    float* outp = g_qkv + (size_t)b * QKV_ROWS * NSEQ;
#pragma unroll
    for (int mt = 0; mt < 4; mt++) {
        const int row0 = rowBase + warp_m * 64 + mt * 16 + lg;
#pragma unroll
        for (int nt = 0; nt < 4; nt++) {
            const int cn = nBase + warp_n * 32 + nt * 8 + (lc << 1);
            float v0 = acc[mt][nt][0], v1 = acc[mt][nt][1];
            float v2 = acc[mt][nt][2], v3 = acc[mt][nt][3];
            if (grp == 1) { v0 = __expf(v0); v1 = __expf(v1); v2 = __expf(v2); v3 = __expf(v3); }
            *(float2*)(outp + (size_t)row0 * NSEQ + cn)       = make_float2(v0, v1);
            *(float2*)(outp + (size_t)(row0 + 8) * NSEQ + cn) = make_float2(v2, v3);
        }
    }
}

// ---------- K2: C[b,h,d,e] += sum_n ek[d,n] v[e,n];  S += sum_n ek ----------
__global__ __launch_bounds__(256) void k_ctx() {
    const int b = blockIdx.z, h = blockIdx.y;
    const int nBase = blockIdx.x * 128;
    const int tid = threadIdx.x;

    __shared__ float ek[32][129];
    __shared__ float vv[32][129];

    const float* ekg = g_qkv + ((size_t)(b * QKV_ROWS + 128 + h * DHEAD)) * NSEQ + nBase;
    const float* vg  = g_qkv + ((size_t)(b * QKV_ROWS + 256 + h * DHEAD)) * NSEQ + nBase;

    for (int i = tid; i < 32 * 32; i += 256) {
        int r = i >> 5, c4 = (i & 31) << 2;
        float4 t = *(const float4*)(ekg + (size_t)r * NSEQ + c4);
        ek[r][c4 + 0] = t.x; ek[r][c4 + 1] = t.y; ek[r][c4 + 2] = t.z; ek[r][c4 + 3] = t.w;
        float4 u = *(const float4*)(vg + (size_t)r * NSEQ + c4);
        vv[r][c4 + 0] = u.x; vv[r][c4 + 1] = u.y; vv[r][c4 + 2] = u.z; vv[r][c4 + 3] = u.w;
    }
    __syncthreads();

    const int d  = tid >> 3;
    const int e0 = (tid & 7) << 2;
    float a0 = 0.f, a1 = 0.f, a2 = 0.f, a3 = 0.f, s = 0.f;
#pragma unroll 8
    for (int n = 0; n < 128; n++) {
        float kv = ek[d][n];
        s  += kv;
        a0 += kv * vv[e0 + 0][n];
        a1 += kv * vv[e0 + 1][n];
        a2 += kv * vv[e0 + 2][n];
        a3 += kv * vv[e0 + 3][n];
    }
    float* Cb = g_C + (size_t)(((b * HEADS + h) * DHEAD + d) * DHEAD + e0);
    atomicAdd(Cb + 0, a0); atomicAdd(Cb + 1, a1);
    atomicAdd(Cb + 2, a2); atomicAdd(Cb + 3, a3);
    if (e0 == 0) atomicAdd(g_S + (b * HEADS + h) * DHEAD + d, s);
}

// ---------- K3: G[b][o][h*32+d] = (sum_e w_out[o][h*32+e] * C[b,h,d,e]) / S[b,h,d] ----------
__global__ __launch_bounds__(256) void k_G(const float* __restrict__ w_out) {
    const int h = blockIdx.x, b = blockIdx.y;
    const int o = threadIdx.x;

    __shared__ float Cs[DHEAD * DHEAD];
    __shared__ float Si[DHEAD];

    for (int i = threadIdx.x; i < DHEAD * DHEAD; i += 256)
        Cs[i] = g_C[(size_t)(b * HEADS + h) * DHEAD * DHEAD + i];
    if (threadIdx.x < DHEAD)
        Si[threadIdx.x] = __frcp_rn(g_S[(b * HEADS + h) * DHEAD + threadIdx.x]);
    __syncthreads();

    float wr[DHEAD];
#pragma unroll
    for (int e4 = 0; e4 < DHEAD; e4 += 4) {
        float4 t = *(const float4*)(w_out + (size_t)o * HID + h * DHEAD + e4);
        wr[e4] = t.x; wr[e4 + 1] = t.y; wr[e4 + 2] = t.z; wr[e4 + 3] = t.w;
    }
    float* Gp = g_G + ((size_t)b * DIM + o) * HID + h * DHEAD;
#pragma unroll 4
    for (int d = 0; d < DHEAD; d++) {
        float acc = 0.f;
#pragma unroll
        for (int e = 0; e < DHEAD; e++)
            acc += wr[e] * Cs[d * DHEAD + e];
        Gp[d] = acc * Si[d];
    }
}

// ---------- K4: out = G_b @ q_b + b_out via mma.sync tf32 3-pass ----------
// grid (N/128, 2, B), block 256. CTA tile 128x128, K=128 in 4 chunks of 32.
__global__ __launch_bounds__(256, 2) void k_out_mma(const float* __restrict__ bias,
                                                    float* __restrict__ out) {
    extern __shared__ float sm[];
    const int b       = blockIdx.z;
    const int rowBase = blockIdx.y * 128;
    const int nBase   = blockIdx.x * 128;
    const int tid     = threadIdx.x;
    const int lane    = tid & 31;
    const int wid     = tid >> 5;
    const int warp_m  = wid & 1;
    const int warp_n  = wid >> 1;

    const float* A  = g_G + (size_t)b * DIM * HID;
    const float* Bq = g_qkv + (size_t)b * QKV_ROWS * NSEQ + nBase;  // q rows [0,128)

    float acc[4][4][4];
#pragma unroll
    for (int i = 0; i < 4; i++)
#pragma unroll
        for (int j = 0; j < 4; j++)
#pragma unroll
            for (int c = 0; c < 4; c++) acc[i][j][c] = 0.0f;

    const int lg = lane >> 2;
    const int lc = lane & 3;

    for (int chunk = 0; chunk < 4; chunk++) {
        const int k0 = chunk * 32;
#pragma unroll
        for (int it = 0; it < 4; it++) {
            const int i  = tid + it * 256;
            const int r  = i >> 3;
            const int c4 = (i & 7) << 2;
            float4 t = *(const float4*)(A + (size_t)(rowBase + r) * HID + k0 + c4);
            float4 hi, lo; tf32_split4(t, hi, lo);
            *(float4*)&sm[A_HI + r * 36 + c4] = hi;
            *(float4*)&sm[A_LO + r * 36 + c4] = lo;
        }
#pragma unroll
        for (int it = 0; it < 4; it++) {
            const int i  = tid + it * 256;
            const int k  = i >> 5;
            const int n4 = (i & 31) << 2;
            float4 t = *(const float4*)(Bq + (size_t)(k0 + k) * NSEQ + n4);
            float4 hi, lo; tf32_split4(t, hi, lo);
            *(float4*)&sm[B_HI + k * 136 + n4] = hi;
            *(float4*)&sm[B_LO + k * 136 + n4] = lo;
        }
        __syncthreads();

#pragma unroll
        for (int ks = 0; ks < 4; ks++) {
            const int kb = ks * 8;
            uint32_t bh[4][2], bl[4][2];
#pragma unroll
            for (int nt = 0; nt < 4; nt++) {
                const int n0 = warp_n * 32 + nt * 8 + lg;
                const int r0 = (kb + lc) * 136 + n0;
                bh[nt][0] = __float_as_uint(sm[B_HI + r0]);
                bh[nt][1] = __float_as_uint(sm[B_HI + r0 + 4 * 136]);
                bl[nt][0] = __float_as_uint(sm[B_LO + r0]);
                bl[nt][1] = __float_as_uint(sm[B_LO + r0 + 4 * 136]);
            }
#pragma unroll
            for (int mt = 0; mt < 4; mt++) {
                const int m0 = warp_m * 64 + mt * 16 + lg;
                const int a0o = m0 * 36 + kb + lc;
                const uint32_t ah0 = __float_as_uint(sm[A_HI + a0o]);
                const uint32_t ah1 = __float_as_uint(sm[A_HI + a0o + 8 * 36]);
                const uint32_t ah2 = __float_as_uint(sm[A_HI + a0o + 4]);
                const uint32_t ah3 = __float_as_uint(sm[A_HI + a0o + 8 * 36 + 4]);
                const uint32_t al0 = __float_as_uint(sm[A_LO + a0o]);
                const uint32_t al1 = __float_as_uint(sm[A_LO + a0o + 8 * 36]);
                const uint32_t al2 = __float_as_uint(sm[A_LO + a0o + 4]);
                const uint32_t al3 = __float_as_uint(sm[A_LO + a0o + 8 * 36 + 4]);
#pragma unroll
                for (int nt = 0; nt < 4; nt++) {
                    MMA_TF32(acc[mt][nt], ah0, ah1, ah2, ah3, bh[nt][0], bh[nt][1]);
                    MMA_TF32(acc[mt][nt], ah0, ah1, ah2, ah3, bl[nt][0], bl[nt][1]);
                    MMA_TF32(acc[mt][nt], al0, al1, al2, al3, bh[nt][0], bh[nt][1]);
                }
            }
        }
        __syncthreads();
    }

    float* outb = out + (size_t)b * DIM * NSEQ;
#pragma unroll
    for (int mt = 0; mt < 4; mt++) {
        const int row0 = rowBase + warp_m * 64 + mt * 16 + lg;
        const float bi0 = bias[row0], bi1 = bias[row0 + 8];
#pragma unroll
        for (int nt = 0; nt < 4; nt++) {
            const int cn = nBase + warp_n * 32 + nt * 8 + (lc << 1);
            *(float2*)(outb + (size_t)row0 * NSEQ + cn) =
                make_float2(acc[mt][nt][0] + bi0, acc[mt][nt][1] + bi0);
            *(float2*)(outb + (size_t)(row0 + 8) * NSEQ + cn) =
                make_float2(acc[mt][nt][2] + bi1, acc[mt][nt][3] + bi1);
        }
    }
}

extern "C" void kernel_launch(void* const* d_in, const int* in_sizes, int n_in,
                              void* d_out, int out_size) {
    const float* x     = (const float*)d_in[0];
    const float* w_qkv = (const float*)d_in[1];
    const float* w_out = (const float*)d_in[2];
    const float* b_out = (const float*)d_in[3];
    float* out = (float*)d_out;

    cudaFuncSetAttribute(k_qkv_mma, cudaFuncAttributeMaxDynamicSharedMemorySize, DSMEM_BYTES);
    cudaFuncSetAttribute(k_out_mma, cudaFuncAttributeMaxDynamicSharedMemorySize, DSMEM_BYTES);

    k_zero<<<257, 256>>>();
    k_qkv_mma<<<dim3(NSEQ / 128, 3, BATCH), 256, DSMEM_BYTES>>>(x, w_qkv);
    k_ctx<<<dim3(NSEQ / 128, HEADS, BATCH), 256>>>();
    k_G<<<dim3(HEADS, BATCH), 256>>>(w_out);
    k_out_mma<<<dim3(NSEQ / 128, 2, BATCH), 256, DSMEM_BYTES>>>(b_out, out);
}

// round 4
// speedup vs baseline: 1.6057x; 1.3979x over previous
#include <cuda_runtime.h>
#include <cstdint>

#define BATCH 16
#define DIM   256
#define NSEQ  8192
#define QKV_ROWS 384
#define HEADS 4
#define DHEAD 32
#define HID   128

// Scratch (device globals — no runtime allocation allowed)
__device__ float g_qkv[(size_t)BATCH * QKV_ROWS * NSEQ];   // q raw | exp(k) | v
__device__ float g_C[BATCH * HEADS * DHEAD * DHEAD];       // context numerator
__device__ float g_S[BATCH * HEADS * DHEAD];               // softmax denominator
__device__ float g_G[BATCH * DIM * HID];                   // collapsed tail matrix

// ===================== mma.sync bf16 m16n8k16 (sm_80+ PTX, legal on sm_103) ==================
#define MMA_BF16(d, a0, a1, a2, a3, b0, b1) \
    asm volatile("mma.sync.aligned.m16n8k16.row.col.f32.bf16.bf16.f32 " \
        "{%0,%1,%2,%3}, {%4,%5,%6,%7}, {%8,%9}, {%0,%1,%2,%3};" \
        : "+f"((d)[0]), "+f"((d)[1]), "+f"((d)[2]), "+f"((d)[3]) \
        : "r"(a0), "r"(a1), "r"(a2), "r"(a3), "r"(b0), "r"(b1))

// pack two floats to bf16x2: lo half = first arg, hi half = second arg
__device__ __forceinline__ uint32_t pack_bf16(float lo, float hi) {
    uint32_t r;
    asm("cvt.rn.bf16x2.f32 %0, %1, %2;" : "=r"(r) : "f"(hi), "f"(lo));
    return r;
}
// split pair (x,y) -> hi-plane packed + mid-plane packed (residual after bf16 round)
__device__ __forceinline__ void bf16_split2(float x, float y, uint32_t& hp, uint32_t& mp) {
    hp = pack_bf16(x, y);
    float fx = __uint_as_float(hp << 16);
    float fy = __uint_as_float(hp & 0xFFFF0000u);
    mp = pack_bf16(x - fx, y - fy);
}

// Shared tiles, halves (bf16), row stride 40 halves (20 words) -> conflict-free frag LDS
#define KP 40

// ---------- K0: zero the accumulators ----------
__global__ void k_zero() {
    int i = blockIdx.x * 256 + threadIdx.x;
    if (i < BATCH * HEADS * DHEAD * DHEAD) g_C[i] = 0.0f;
    if (i < BATCH * HEADS * DHEAD)         g_S[i] = 0.0f;
}

// ================= shared GEMM core (A[m][k] natural, B transposed to [n][k]) ===============
// A rows <- Asrc (lda), B from Bsrc[k][n] (ldb = NSEQ), CTA tile 128x128, chunk K=32.
struct SmTiles {
    uint16_t Ah[128 * KP];
    uint16_t Am[128 * KP];
    uint16_t Bh[128 * KP];
    uint16_t Bm[128 * KP];
};

__device__ __forceinline__ void load_A_chunk(SmTiles* sm, const float* Asrc, int lda,
                                             int k0, int tid) {
#pragma unroll
    for (int it = 0; it < 4; it++) {
        const int i  = tid + it * 256;
        const int r  = i >> 3;
        const int c4 = (i & 7) << 2;
        float4 t = *(const float4*)(Asrc + (size_t)r * lda + k0 + c4);
        uint32_t h01, m01, h23, m23;
        bf16_split2(t.x, t.y, h01, m01);
        bf16_split2(t.z, t.w, h23, m23);
        *(uint2*)&sm->Ah[r * KP + c4] = make_uint2(h01, h23);
        *(uint2*)&sm->Am[r * KP + c4] = make_uint2(m01, m23);
    }
}

// B loader with in-register transpose: warp covers 8 k-rows x 16 n per iter.
__device__ __forceinline__ void load_B_chunk(SmTiles* sm, const float* Bsrc,
                                             int k0, int tid) {
    const int lane = tid & 31;
    const int w    = tid >> 5;
    const int a    = lane >> 3;          // k-pair index within iter (0..3)
    const int p    = (lane >> 2) & 1;    // k parity
    const int nq   = lane & 3;           // n quad
    const int n4   = w * 16 + nq * 4;
#pragma unroll
    for (int it = 0; it < 4; it++) {
        const int kloc = it * 8 + 2 * a + p;
        float4 t = *(const float4*)(Bsrc + (size_t)(k0 + kloc) * NSEQ + n4);
        // exchange with k-parity partner (lane ^ 4): same n4, other parity
        float y0 = __shfl_xor_sync(0xFFFFFFFFu, t.x, 4);
        float y1 = __shfl_xor_sync(0xFFFFFFFFu, t.y, 4);
        float y2 = __shfl_xor_sync(0xFFFFFFFFu, t.z, 4);
        float y3 = __shfl_xor_sync(0xFFFFFFFFu, t.w, 4);
        // parity 0 lane stores n4+0,+1 ; parity 1 lane stores n4+2,+3
        float e0, o0, e1, o1;
        int j0, j1;
        if (p == 0) { j0 = 0; j1 = 1; e0 = t.x; o0 = y0; e1 = t.y; o1 = y1; }
        else        { j0 = 2; j1 = 3; e0 = y2; o0 = t.z; e1 = y3; o1 = t.w; }
        const int cw = it * 4 + a;       // k-pair word column (0..15)
        uint32_t h, m;
        bf16_split2(e0, o0, h, m);       // lo = even k, hi = odd k
        ((uint32_t*)&sm->Bh[(n4 + j0) * KP])[cw] = h;
        ((uint32_t*)&sm->Bm[(n4 + j0) * KP])[cw] = m;
        bf16_split2(e1, o1, h, m);
        ((uint32_t*)&sm->Bh[(n4 + j1) * KP])[cw] = h;
        ((uint32_t*)&sm->Bm[(n4 + j1) * KP])[cw] = m;
    }
}

__device__ __forceinline__ void mma_chunk(SmTiles* sm, float acc[4][4][4],
                                          int warp_m, int warp_n, int lane) {
    const int lg = lane >> 2;
    const int lc = lane & 3;
    const uint32_t* AhW = (const uint32_t*)sm->Ah;
    const uint32_t* AmW = (const uint32_t*)sm->Am;
    const uint32_t* BhW = (const uint32_t*)sm->Bh;
    const uint32_t* BmW = (const uint32_t*)sm->Bm;
#pragma unroll
    for (int ks = 0; ks < 2; ks++) {
        uint32_t bh[4][2], bm[4][2];
#pragma unroll
        for (int nt = 0; nt < 4; nt++) {
            const int wb = (warp_n * 32 + nt * 8 + lg) * (KP / 2) + ks * 8 + lc;
            bh[nt][0] = BhW[wb]; bh[nt][1] = BhW[wb + 4];
            bm[nt][0] = BmW[wb]; bm[nt][1] = BmW[wb + 4];
        }
#pragma unroll
        for (int mt = 0; mt < 4; mt++) {
            const int wa = (warp_m * 64 + mt * 16 + lg) * (KP / 2) + ks * 8 + lc;
            const uint32_t ah0 = AhW[wa],       ah1 = AhW[wa + 8 * (KP / 2)];
            const uint32_t ah2 = AhW[wa + 4],   ah3 = AhW[wa + 8 * (KP / 2) + 4];
            const uint32_t am0 = AmW[wa],       am1 = AmW[wa + 8 * (KP / 2)];
            const uint32_t am2 = AmW[wa + 4],   am3 = AmW[wa + 8 * (KP / 2) + 4];
#pragma unroll
            for (int nt = 0; nt < 4; nt++) {
                MMA_BF16(acc[mt][nt], ah0, ah1, ah2, ah3, bh[nt][0], bh[nt][1]);
                MMA_BF16(acc[mt][nt], ah0, ah1, ah2, ah3, bm[nt][0], bm[nt][1]);
                MMA_BF16(acc[mt][nt], am0, am1, am2, am3, bh[nt][0], bh[nt][1]);
            }
        }
    }
}

// ---------- K1: qkv = w_qkv @ x ----------
__global__ __launch_bounds__(256, 2) void k_qkv_mma(const float* __restrict__ x,
                                                    const float* __restrict__ w) {
    __shared__ SmTiles sm;
    const int b       = blockIdx.z;
    const int grp     = blockIdx.y;
    const int rowBase = grp * 128;
    const int nBase   = blockIdx.x * 128;
    const int tid     = threadIdx.x;
    const int lane    = tid & 31;
    const int wid     = tid >> 5;
    const int warp_m  = wid & 1;
    const int warp_n  = wid >> 1;

    const float* xb = x + (size_t)b * DIM * NSEQ + nBase;
    const float* wA = w + (size_t)rowBase * DIM;

    float acc[4][4][4];
#pragma unroll
    for (int i = 0; i < 4; i++)
#pragma unroll
        for (int j = 0; j < 4; j++)
#pragma unroll
            for (int c = 0; c < 4; c++) acc[i][j][c] = 0.0f;

    for (int chunk = 0; chunk < 8; chunk++) {
        const int k0 = chunk * 32;
        load_A_chunk(&sm, wA, DIM, k0, tid);
        load_B_chunk(&sm, xb, k0, tid);
        __syncthreads();
        mma_chunk(&sm, acc, warp_m, warp_n, lane);
        __syncthreads();
    }

    const int lg = lane >> 2, lc = lane & 3;
    float* outp = g_qkv + (size_t)b * QKV_ROWS * NSEQ;
#pragma unroll
    for (int mt = 0; mt < 4; mt++) {
        const int row0 = rowBase + warp_m * 64 + mt * 16 + lg;
#pragma unroll
        for (int nt = 0; nt < 4; nt++) {
            const int cn = nBase + warp_n * 32 + nt * 8 + (lc << 1);
            float v0 = acc[mt][nt][0], v1 = acc[mt][nt][1];
            float v2 = acc[mt][nt][2], v3 = acc[mt][nt][3];
            if (grp == 1) { v0 = __expf(v0); v1 = __expf(v1); v2 = __expf(v2); v3 = __expf(v3); }
            *(float2*)(outp + (size_t)row0 * NSEQ + cn)       = make_float2(v0, v1);
            *(float2*)(outp + (size_t)(row0 + 8) * NSEQ + cn) = make_float2(v2, v3);
        }
    }
}

// ---------- K2: C[b,h,d,e] += sum_n ek[d,n] v[e,n];  S += sum_n ek ----------
__global__ __launch_bounds__(256) void k_ctx() {
    const int b = blockIdx.z, h = blockIdx.y;
    const int nBase = blockIdx.x * 128;
    const int tid = threadIdx.x;

    __shared__ float ek[32][129];
    __shared__ float vv[32][129];

    const float* ekg = g_qkv + ((size_t)(b * QKV_ROWS + 128 + h * DHEAD)) * NSEQ + nBase;
    const float* vg  = g_qkv + ((size_t)(b * QKV_ROWS + 256 + h * DHEAD)) * NSEQ + nBase;

    for (int i = tid; i < 32 * 32; i += 256) {
        int r = i >> 5, c4 = (i & 31) << 2;
        float4 t = *(const float4*)(ekg + (size_t)r * NSEQ + c4);
        ek[r][c4 + 0] = t.x; ek[r][c4 + 1] = t.y; ek[r][c4 + 2] = t.z; ek[r][c4 + 3] = t.w;
        float4 u = *(const float4*)(vg + (size_t)r * NSEQ + c4);
        vv[r][c4 + 0] = u.x; vv[r][c4 + 1] = u.y; vv[r][c4 + 2] = u.z; vv[r][c4 + 3] = u.w;
    }
    __syncthreads();

    const int d  = tid >> 3;
    const int e0 = (tid & 7) << 2;
    float a0 = 0.f, a1 = 0.f, a2 = 0.f, a3 = 0.f, s = 0.f;
#pragma unroll 8
    for (int n = 0; n < 128; n++) {
        float kv = ek[d][n];
        s  += kv;
        a0 += kv * vv[e0 + 0][n];
        a1 += kv * vv[e0 + 1][n];
        a2 += kv * vv[e0 + 2][n];
        a3 += kv * vv[e0 + 3][n];
    }
    float* Cb = g_C + (size_t)(((b * HEADS + h) * DHEAD + d) * DHEAD + e0);
    atomicAdd(Cb + 0, a0); atomicAdd(Cb + 1, a1);
    atomicAdd(Cb + 2, a2); atomicAdd(Cb + 3, a3);
    if (e0 == 0) atomicAdd(g_S + (b * HEADS + h) * DHEAD + d, s);
}

// ---------- K3: G = (w_out-slice @ C) / S ----------
__global__ __launch_bounds__(256) void k_G(const float* __restrict__ w_out) {
    const int h = blockIdx.x, b = blockIdx.y;
    const int o = threadIdx.x;

    __shared__ float Cs[DHEAD * DHEAD];
    __shared__ float Si[DHEAD];

    for (int i = threadIdx.x; i < DHEAD * DHEAD; i += 256)
        Cs[i] = g_C[(size_t)(b * HEADS + h) * DHEAD * DHEAD + i];
    if (threadIdx.x < DHEAD)
        Si[threadIdx.x] = __frcp_rn(g_S[(b * HEADS + h) * DHEAD + threadIdx.x]);
    __syncthreads();

    float wr[DHEAD];
#pragma unroll
    for (int e4 = 0; e4 < DHEAD; e4 += 4) {
        float4 t = *(const float4*)(w_out + (size_t)o * HID + h * DHEAD + e4);
        wr[e4] = t.x; wr[e4 + 1] = t.y; wr[e4 + 2] = t.z; wr[e4 + 3] = t.w;
    }
    float* Gp = g_G + ((size_t)b * DIM + o) * HID + h * DHEAD;
#pragma unroll 4
    for (int d = 0; d < DHEAD; d++) {
        float acc = 0.f;
#pragma unroll
        for (int e = 0; e < DHEAD; e++)
            acc += wr[e] * Cs[d * DHEAD + e];
        Gp[d] = acc * Si[d];
    }
}

// ---------- K4: out = G_b @ q_b + b_out ----------
__global__ __launch_bounds__(256, 2) void k_out_mma(const float* __restrict__ bias,
                                                    float* __restrict__ out) {
    __shared__ SmTiles sm;
    const int b       = blockIdx.z;
    const int rowBase = blockIdx.y * 128;
    const int nBase   = blockIdx.x * 128;
    const int tid     = threadIdx.x;
    const int lane    = tid & 31;
    const int wid     = tid >> 5;
    const int warp_m  = wid & 1;
    const int warp_n  = wid >> 1;

    const float* A  = g_G + (size_t)b * DIM * HID + (size_t)rowBase * HID;
    const float* Bq = g_qkv + (size_t)b * QKV_ROWS * NSEQ + nBase;  // q rows [0,128)

    float acc[4][4][4];
#pragma unroll
    for (int i = 0; i < 4; i++)
#pragma unroll
        for (int j = 0; j < 4; j++)
#pragma unroll
            for (int c = 0; c < 4; c++) acc[i][j][c] = 0.0f;

    for (int chunk = 0; chunk < 4; chunk++) {
        const int k0 = chunk * 32;
        load_A_chunk(&sm, A, HID, k0, tid);
        load_B_chunk(&sm, Bq, k0, tid);
        __syncthreads();
        mma_chunk(&sm, acc, warp_m, warp_n, lane);
        __syncthreads();
    }

    const int lg = lane >> 2, lc = lane & 3;
    float* outb = out + (size_t)b * DIM * NSEQ;
#pragma unroll
    for (int mt = 0; mt < 4; mt++) {
        const int row0 = rowBase + warp_m * 64 + mt * 16 + lg;
        const float bi0 = bias[row0], bi1 = bias[row0 + 8];
#pragma unroll
        for (int nt = 0; nt < 4; nt++) {
            const int cn = nBase + warp_n * 32 + nt * 8 + (lc << 1);
            *(float2*)(outb + (size_t)row0 * NSEQ + cn) =
                make_float2(acc[mt][nt][0] + bi0, acc[mt][nt][1] + bi0);
            *(float2*)(outb + (size_t)(row0 + 8) * NSEQ + cn) =
                make_float2(acc[mt][nt][2] + bi1, acc[mt][nt][3] + bi1);
        }
    }
}

extern "C" void kernel_launch(void* const* d_in, const int* in_sizes, int n_in,
                              void* d_out, int out_size) {
    const float* x     = (const float*)d_in[0];
    const float* w_qkv = (const float*)d_in[1];
    const float* w_out = (const float*)d_in[2];
    const float* b_out = (const float*)d_in[3];
    float* out = (float*)d_out;

    k_zero<<<257, 256>>>();
    k_qkv_mma<<<dim3(NSEQ / 128, 3, BATCH), 256>>>(x, w_qkv);
    k_ctx<<<dim3(NSEQ / 128, HEADS, BATCH), 256>>>();
    k_G<<<dim3(HEADS, BATCH), 256>>>(w_out);
    k_out_mma<<<dim3(NSEQ / 128, 2, BATCH), 256>>>(b_out, out);
}